// round 2
// baseline (speedup 1.0000x reference)
#include <cuda_runtime.h>
#include <cuda_bf16.h>
#include <math.h>

// Problem constants (fixed by the reference)
#define NN      100000
#define F_IN    256
#define HID     64          // H1*C1
#define H1      8
#define C1      8
#define NC      40
#define E_MAX   1700000     // E + N self loops
#define NEG_SLOPE 0.2f
#define NEG_BIG  -3.0e38f

// ---------------- scratch (device globals; no cudaMalloc allowed) -------------
__device__ int   g_is64;
__device__ int   g_src[E_MAX];
__device__ int   g_dst[E_MAX];
__device__ int   g_deg[NN];
__device__ int   g_rowptr[NN + 1];
__device__ int   g_fill[NN];
__device__ int   g_col[E_MAX];
__device__ int   g_bsum[256];
__device__ float g_h1[(long)NN * HID];
__device__ float g_as1[NN * H1];
__device__ float g_ad1[NN * H1];
__device__ float g_h1o[(long)NN * HID];
__device__ float g_h2[(long)NN * NC];
__device__ float g_as2[NN];
__device__ float g_ad2[NN];

// ---------------- dtype detection + edge conversion --------------------------
// If edge_index is really int64, all sampled values are valid node ids < NN.
// If it is int32 misread as int64, values fuse two ids -> almost surely >= 2^32.
__global__ void k_detect(const void* ei, int EC) {
    __shared__ int bad;
    if (threadIdx.x == 0) bad = 0;
    __syncthreads();
    const long long* p = (const long long*)ei;
    int n = EC < 1024 ? EC : 1024;
    if ((int)threadIdx.x < n) {
        long long v = p[threadIdx.x];
        if (v < 0 || v >= NN) atomicExch(&bad, 1);
    }
    __syncthreads();
    if (threadIdx.x == 0) g_is64 = bad ? 0 : 1;
}

__global__ void k_convert(const void* ei, int EC) {
    int i = blockIdx.x * blockDim.x + threadIdx.x;
    if (i >= EC) return;
    if (g_is64) {
        const long long* p = (const long long*)ei;
        g_src[i] = (int)p[i];
        g_dst[i] = (int)p[EC + i];
    } else {
        const int* p = (const int*)ei;
        g_src[i] = p[i];
        g_dst[i] = p[EC + i];
    }
}

// ---------------- CSR build --------------------------------------------------
__global__ void k_zero_deg() {
    int i = blockIdx.x * blockDim.x + threadIdx.x;
    if (i < NN) g_deg[i] = 0;
}

__global__ void k_hist(int EC) {
    int i = blockIdx.x * blockDim.x + threadIdx.x;
    if (i < EC) {
        int d = g_dst[i];
        if (d >= 0 && d < NN) atomicAdd(&g_deg[d], 1);
    }
}

// per-block exclusive scan of g_deg -> g_rowptr, block totals -> g_bsum
__global__ void k_scan_block() {
    __shared__ int ws[32];
    int tid = threadIdx.x;
    int gid = blockIdx.x * 1024 + tid;
    int v = (gid < NN) ? g_deg[gid] : 0;
    int x = v;
    #pragma unroll
    for (int o = 1; o < 32; o <<= 1) {
        int t = __shfl_up_sync(0xffffffffu, x, o);
        if ((tid & 31) >= o) x += t;
    }
    if ((tid & 31) == 31) ws[tid >> 5] = x;
    __syncthreads();
    if (tid < 32) {
        int w = ws[tid];
        int y = w;
        #pragma unroll
        for (int o = 1; o < 32; o <<= 1) {
            int t = __shfl_up_sync(0xffffffffu, y, o);
            if (tid >= o) y += t;
        }
        ws[tid] = y - w;   // exclusive prefix of warp sums
    }
    __syncthreads();
    int incl = x + ws[tid >> 5];
    if (gid < NN) g_rowptr[gid] = incl - v;  // exclusive
    if (tid == 1023) g_bsum[blockIdx.x] = incl;
}

__global__ void k_scan_tops(int nblocks) {
    if (threadIdx.x == 0 && blockIdx.x == 0) {
        int run = 0;
        for (int b = 0; b < nblocks; b++) {
            int t = g_bsum[b];
            g_bsum[b] = run;
            run += t;
        }
    }
}

__global__ void k_scan_fix(int EC) {
    int gid = blockIdx.x * 1024 + threadIdx.x;
    if (gid < NN) {
        int v = g_rowptr[gid] + g_bsum[gid >> 10];
        g_rowptr[gid] = v;
        g_fill[gid] = v;
    }
    if (gid == 0) g_rowptr[NN] = EC;
}

__global__ void k_scatter(int EC) {
    int i = blockIdx.x * blockDim.x + threadIdx.x;
    if (i < EC) {
        int s = g_src[i];
        int d = g_dst[i];
        if (d >= 0 && d < NN) {
            int p = atomicAdd(&g_fill[d], 1);
            if (p >= 0 && p < E_MAX) g_col[p] = s;
        }
    }
}

// ---------------- GEMM1: h1 = x @ W1  (M=100000, K=256, N=64) ----------------
__global__ void k_gemm1(const float* __restrict__ X, const float* __restrict__ W) {
    __shared__ float As[64][33];
    __shared__ float Bs[32][64];
    int tid = threadIdx.x;           // 256 threads
    int r0 = blockIdx.x * 64;
    int tx = tid & 15, ty = tid >> 4;
    float acc[4][4];
    #pragma unroll
    for (int i = 0; i < 4; i++)
        #pragma unroll
        for (int j = 0; j < 4; j++) acc[i][j] = 0.f;

    for (int k0 = 0; k0 < F_IN; k0 += 32) {
        #pragma unroll
        for (int l = 0; l < 2; l++) {
            int slot = tid + l * 256;
            int row = slot >> 3;         // 0..63
            int kv = slot & 7;           // 0..7 (float4 within 32)
            int gr = r0 + row;
            float4 v = make_float4(0.f, 0.f, 0.f, 0.f);
            if (gr < NN) v = *(const float4*)(X + (long)gr * F_IN + k0 + kv * 4);
            As[row][kv * 4 + 0] = v.x;
            As[row][kv * 4 + 1] = v.y;
            As[row][kv * 4 + 2] = v.z;
            As[row][kv * 4 + 3] = v.w;
        }
        #pragma unroll
        for (int l = 0; l < 2; l++) {
            int slot = tid + l * 256;
            int kk = slot >> 4;          // 0..31
            int cv = slot & 15;          // 0..15
            *(float4*)&Bs[kk][cv * 4] = *(const float4*)(W + (k0 + kk) * HID + cv * 4);
        }
        __syncthreads();
        #pragma unroll
        for (int kk = 0; kk < 32; kk++) {
            float a[4], b[4];
            #pragma unroll
            for (int i = 0; i < 4; i++) a[i] = As[ty * 4 + i][kk];
            float4 bv = *(const float4*)&Bs[kk][tx * 4];
            b[0] = bv.x; b[1] = bv.y; b[2] = bv.z; b[3] = bv.w;
            #pragma unroll
            for (int i = 0; i < 4; i++)
                #pragma unroll
                for (int j = 0; j < 4; j++)
                    acc[i][j] += a[i] * b[j];
        }
        __syncthreads();
    }
    #pragma unroll
    for (int i = 0; i < 4; i++) {
        int gr = r0 + ty * 4 + i;
        if (gr < NN) {
            #pragma unroll
            for (int j = 0; j < 4; j++)
                g_h1[(long)gr * HID + tx * 4 + j] = acc[i][j];
        }
    }
}

// ---------------- alpha for layer 1 ------------------------------------------
__global__ void k_alpha1(const float* __restrict__ att_s, const float* __restrict__ att_d) {
    int t = blockIdx.x * blockDim.x + threadIdx.x;
    if (t >= NN * H1) return;
    int n = t >> 3, h = t & 7;
    const float4* hp = (const float4*)(g_h1 + (long)n * HID + h * C1);
    float4 x0 = hp[0], x1 = hp[1];
    const float4* sp = (const float4*)(att_s + h * C1);
    float4 s0 = __ldg(sp), s1 = __ldg(sp + 1);
    const float4* dp = (const float4*)(att_d + h * C1);
    float4 d0 = __ldg(dp), d1 = __ldg(dp + 1);
    float as = x0.x * s0.x + x0.y * s0.y + x0.z * s0.z + x0.w * s0.w
             + x1.x * s1.x + x1.y * s1.y + x1.z * s1.z + x1.w * s1.w;
    float ad = x0.x * d0.x + x0.y * d0.y + x0.z * d0.z + x0.w * d0.w
             + x1.x * d1.x + x1.y * d1.y + x1.z * d1.z + x1.w * d1.w;
    g_as1[t] = as;
    g_ad1[t] = ad;
}

// ---------------- layer 1 aggregation (warp per dst) + elu -------------------
__global__ void k_agg1(const float* __restrict__ b1) {
    int warp = (blockIdx.x * blockDim.x + threadIdx.x) >> 5;
    int lane = threadIdx.x & 31;
    if (warp >= NN) return;
    int d = warp;
    int start = g_rowptr[d], end = g_rowptr[d + 1];
    int hid = lane & 7;
    int grp = lane >> 3;          // 0..3: edge sub-group
    float ad = g_ad1[d * H1 + hid];

    // pass 1: per-head max over edges
    float mx = NEG_BIG;
    for (int i = start + grp; i < end; i += 4) {
        int s = g_col[i];
        float e = g_as1[s * H1 + hid] + ad;
        e = (e > 0.f) ? e : NEG_SLOPE * e;
        mx = fmaxf(mx, e);
    }
    mx = fmaxf(mx, __shfl_xor_sync(0xffffffffu, mx, 8));
    mx = fmaxf(mx, __shfl_xor_sync(0xffffffffu, mx, 16));

    // pass 2: per-head denom
    float dn = 0.f;
    for (int i = start + grp; i < end; i += 4) {
        int s = g_col[i];
        float e = g_as1[s * H1 + hid] + ad;
        e = (e > 0.f) ? e : NEG_SLOPE * e;
        dn += __expf(e - mx);
    }
    dn += __shfl_xor_sync(0xffffffffu, dn, 8);
    dn += __shfl_xor_sync(0xffffffffu, dn, 16);
    float rdn = 1.0f / dn;

    // pass 3: weighted gather-accumulate; lane = channel (lane, lane+32)
    float acc0 = 0.f, acc1 = 0.f;
    int hA = lane >> 3;           // head of channel 'lane'  (0..3)
    for (int i = start; i < end; ++i) {
        int s = g_col[i];
        float e = g_as1[s * H1 + hid] + ad;
        e = (e > 0.f) ? e : NEG_SLOPE * e;
        float w = __expf(e - mx) * rdn;           // weight for head (lane&7)
        float wA = __shfl_sync(0xffffffffu, w, hA);       // head hA
        float wB = __shfl_sync(0xffffffffu, w, hA + 4);   // head hA+4
        const float* hr = g_h1 + (long)s * HID;
        acc0 += hr[lane] * wA;
        acc1 += hr[lane + 32] * wB;
    }
    float v0 = acc0 + __ldg(b1 + lane);
    float v1 = acc1 + __ldg(b1 + lane + 32);
    v0 = (v0 > 0.f) ? v0 : expm1f(v0);   // elu
    v1 = (v1 > 0.f) ? v1 : expm1f(v1);
    g_h1o[(long)d * HID + lane] = v0;
    g_h1o[(long)d * HID + lane + 32] = v1;
}

// ---------------- GEMM2: h2 = h1o @ W2 (K=64, N=40) + alphas -----------------
__global__ void k_gemm2(const float* __restrict__ W2,
                        const float* __restrict__ att_s2, const float* __restrict__ att_d2) {
    __shared__ float Xs[128][65];
    __shared__ float Ws[HID][NC];
    __shared__ float Sa[NC], Sd[NC];
    int tid = threadIdx.x;           // 128
    int r0 = blockIdx.x * 128;
    for (int f = tid; f < HID * NC; f += 128) Ws[f / NC][f % NC] = W2[f];
    if (tid < NC) { Sa[tid] = att_s2[tid]; Sd[tid] = att_d2[tid]; }
    for (int f = tid; f < 128 * HID; f += 128) {
        int rr = f >> 6, cc = f & 63;
        int gr = r0 + rr;
        Xs[rr][cc] = (gr < NN) ? g_h1o[(long)gr * HID + cc] : 0.f;
    }
    __syncthreads();
    int r = r0 + tid;
    float acc[NC];
    #pragma unroll
    for (int c = 0; c < NC; c++) acc[c] = 0.f;
    #pragma unroll 4
    for (int k = 0; k < HID; k++) {
        float xv = Xs[tid][k];
        #pragma unroll
        for (int c = 0; c < NC; c++) acc[c] += xv * Ws[k][c];
    }
    if (r < NN) {
        float a = 0.f, dd = 0.f;
        #pragma unroll
        for (int c = 0; c < NC; c++) {
            g_h2[(long)r * NC + c] = acc[c];
            a += acc[c] * Sa[c];
            dd += acc[c] * Sd[c];
        }
        g_as2[r] = a;
        g_ad2[r] = dd;
    }
}

// ---------------- layer 2 aggregation + log_softmax (warp per dst) -----------
__global__ void k_agg2(const float* __restrict__ b2, float* __restrict__ out) {
    int warp = (blockIdx.x * blockDim.x + threadIdx.x) >> 5;
    int lane = threadIdx.x & 31;
    if (warp >= NN) return;
    int d = warp;
    int start = g_rowptr[d], end = g_rowptr[d + 1];
    float ad = g_ad2[d];

    float mx = NEG_BIG;
    for (int i = start + lane; i < end; i += 32) {
        float e = g_as2[g_col[i]] + ad;
        e = (e > 0.f) ? e : NEG_SLOPE * e;
        mx = fmaxf(mx, e);
    }
    #pragma unroll
    for (int o = 16; o >= 1; o >>= 1) mx = fmaxf(mx, __shfl_xor_sync(0xffffffffu, mx, o));

    float dn = 0.f;
    for (int i = start + lane; i < end; i += 32) {
        float e = g_as2[g_col[i]] + ad;
        e = (e > 0.f) ? e : NEG_SLOPE * e;
        dn += __expf(e - mx);
    }
    #pragma unroll
    for (int o = 16; o >= 1; o >>= 1) dn += __shfl_xor_sync(0xffffffffu, dn, o);
    float rdn = 1.0f / dn;

    float acc0 = 0.f, acc1 = 0.f;
    for (int i = start; i < end; ++i) {
        int s = g_col[i];
        float e = g_as2[s] + ad;
        e = (e > 0.f) ? e : NEG_SLOPE * e;
        float w = __expf(e - mx) * rdn;
        const float* hr = g_h2 + (long)s * NC;
        acc0 += hr[lane] * w;
        if (lane < 8) acc1 += hr[lane + 32] * w;
    }
    float v0 = acc0 + __ldg(b2 + lane);
    float v1 = (lane < 8) ? (acc1 + __ldg(b2 + lane + 32)) : NEG_BIG;

    // log_softmax over the 40 values held across the warp
    float m = fmaxf(v0, v1);
    #pragma unroll
    for (int o = 16; o >= 1; o >>= 1) m = fmaxf(m, __shfl_xor_sync(0xffffffffu, m, o));
    float se = __expf(v0 - m) + ((lane < 8) ? __expf(v1 - m) : 0.f);
    #pragma unroll
    for (int o = 16; o >= 1; o >>= 1) se += __shfl_xor_sync(0xffffffffu, se, o);
    float lse = m + logf(se);

    out[(long)d * NC + lane] = v0 - lse;
    if (lane < 8) out[(long)d * NC + lane + 32] = v1 - lse;
}

// -----------------------------------------------------------------------------
extern "C" void kernel_launch(void* const* d_in, const int* in_sizes, int n_in,
                              void* d_out, int out_size) {
    const float* x        = (const float*)d_in[0];
    const float* W1       = (const float*)d_in[1];
    const float* att_src1 = (const float*)d_in[2];
    const float* att_dst1 = (const float*)d_in[3];
    const float* b1       = (const float*)d_in[4];
    const float* W2       = (const float*)d_in[5];
    const float* att_src2 = (const float*)d_in[6];
    const float* att_dst2 = (const float*)d_in[7];
    const float* b2       = (const float*)d_in[8];
    const void*  ei       = d_in[9];
    float* out = (float*)d_out;

    int EC = in_sizes[9] / 2;
    if (EC > E_MAX) EC = E_MAX;

    // ---- edge dtype detection + conversion ----
    k_detect<<<1, 1024>>>(ei, EC);
    k_convert<<<(EC + 255) / 256, 256>>>(ei, EC);

    // ---- CSR build (dst-sorted) ----
    k_zero_deg<<<(NN + 255) / 256, 256>>>();
    k_hist<<<(EC + 255) / 256, 256>>>(EC);
    int nblocks = (NN + 1023) / 1024;
    k_scan_block<<<nblocks, 1024>>>();
    k_scan_tops<<<1, 32>>>(nblocks);
    k_scan_fix<<<nblocks, 1024>>>(EC);
    k_scatter<<<(EC + 255) / 256, 256>>>(EC);

    // ---- layer 1 ----
    k_gemm1<<<(NN + 63) / 64, 256>>>(x, W1);
    k_alpha1<<<(NN * H1 + 255) / 256, 256>>>(att_src1, att_dst1);
    k_agg1<<<(NN * 32 + 255) / 256, 256>>>(b1);

    // ---- layer 2 ----
    k_gemm2<<<(NN + 127) / 128, 128>>>(W2, att_src2, att_dst2);
    k_agg2<<<(NN * 32 + 255) / 256, 256>>>(b2, out);
}

// round 4
// speedup vs baseline: 1.1413x; 1.1413x over previous
#include <cuda_runtime.h>
#include <cuda_bf16.h>
#include <math.h>

#define NN      100000
#define F_IN    256
#define HID     64
#define H1      8
#define C1      8
#define NC      40
#define E_MAX   1700000
#define NEG_SLOPE 0.2f

// ---------------- scratch -----------------------------------------------------
__device__ int   g_is64;
__device__ int   g_deg[NN];
__device__ int   g_rowptr[NN + 1];
__device__ int   g_fill[NN];
__device__ int   g_col[E_MAX];
__device__ int   g_bsum[256];
__device__ float g_h1[(long)NN * HID];
__device__ float g_as1[NN * H1];
__device__ float g_ad1[NN * H1];
__device__ float g_h1o[(long)NN * HID];
__device__ float g_h2[(long)NN * NC];
__device__ float g_as2[NN];
__device__ float g_ad2[NN];

// ---------------- edge dtype handling ----------------------------------------
__global__ void k_detect(const void* ei, int EC) {
    __shared__ int bad;
    if (threadIdx.x == 0) bad = 0;
    __syncthreads();
    const long long* p = (const long long*)ei;
    int n = EC < 1024 ? EC : 1024;
    if ((int)threadIdx.x < n) {
        long long v = p[threadIdx.x];
        if (v < 0 || v >= NN) atomicExch(&bad, 1);
    }
    __syncthreads();
    if (threadIdx.x == 0) g_is64 = bad ? 0 : 1;
}

__device__ __forceinline__ int edge_at(const void* ei, int idx) {
    return g_is64 ? (int)((const long long*)ei)[idx] : ((const int*)ei)[idx];
}

// ---------------- CSR build ---------------------------------------------------
__global__ void k_zero_deg() {
    int i = blockIdx.x * blockDim.x + threadIdx.x;
    if (i < NN) g_deg[i] = 0;
}

__global__ void k_hist(const void* ei, int EC) {
    int i = blockIdx.x * blockDim.x + threadIdx.x;
    if (i < EC) {
        int d = edge_at(ei, EC + i);
        if (d >= 0 && d < NN) atomicAdd(&g_deg[d], 1);
    }
}

__global__ void k_scan_block() {
    __shared__ int ws[32];
    int tid = threadIdx.x;
    int gid = blockIdx.x * 1024 + tid;
    int v = (gid < NN) ? g_deg[gid] : 0;
    int x = v;
    #pragma unroll
    for (int o = 1; o < 32; o <<= 1) {
        int t = __shfl_up_sync(0xffffffffu, x, o);
        if ((tid & 31) >= o) x += t;
    }
    if ((tid & 31) == 31) ws[tid >> 5] = x;
    __syncthreads();
    if (tid < 32) {
        int w = ws[tid];
        int y = w;
        #pragma unroll
        for (int o = 1; o < 32; o <<= 1) {
            int t = __shfl_up_sync(0xffffffffu, y, o);
            if (tid >= o) y += t;
        }
        ws[tid] = y - w;
    }
    __syncthreads();
    int incl = x + ws[tid >> 5];
    if (gid < NN) g_rowptr[gid] = incl - v;
    if (tid == 1023) g_bsum[blockIdx.x] = incl;
}

__global__ void k_scan_tops(int nblocks) {
    if (threadIdx.x == 0 && blockIdx.x == 0) {
        int run = 0;
        for (int b = 0; b < nblocks; b++) {
            int t = g_bsum[b];
            g_bsum[b] = run;
            run += t;
        }
    }
}

__global__ void k_scan_fix(int EC) {
    int gid = blockIdx.x * 1024 + threadIdx.x;
    if (gid < NN) {
        int v = g_rowptr[gid] + g_bsum[gid >> 10];
        g_rowptr[gid] = v;
        g_fill[gid] = v;
    }
    if (gid == 0) g_rowptr[NN] = EC;
}

__global__ void k_scatter(const void* ei, int EC) {
    int i = blockIdx.x * blockDim.x + threadIdx.x;
    if (i < EC) {
        int s = edge_at(ei, i);
        int d = edge_at(ei, EC + i);
        if (d >= 0 && d < NN) {
            int p = atomicAdd(&g_fill[d], 1);
            if (p >= 0 && p < E_MAX) g_col[p] = s;
        }
    }
}

// ------- GEMM1 (128x64 tile, 8x4/thread) + fused alpha epilogue ---------------
__global__ void __launch_bounds__(256) k_gemm1(
    const float* __restrict__ X, const float* __restrict__ W,
    const float* __restrict__ att_s, const float* __restrict__ att_d) {
    __shared__ float sm[128 * 65];   // reused: As/Bs during GEMM, hbuf in epilogue
    float* As = sm;                  // [128][33]
    float* Bs = sm + 128 * 33;       // [32][64]  (base 4224 floats -> 16B aligned)
    int tid = threadIdx.x;
    int r0 = blockIdx.x * 128;
    int tx = tid & 15, ty = tid >> 4;
    float acc[8][4];
    #pragma unroll
    for (int i = 0; i < 8; i++)
        #pragma unroll
        for (int j = 0; j < 4; j++) acc[i][j] = 0.f;

    for (int k0 = 0; k0 < F_IN; k0 += 32) {
        #pragma unroll
        for (int l = 0; l < 4; l++) {
            int slot = tid + l * 256;        // 0..1023 float4 slots
            int row = slot >> 3;             // 0..127
            int f4 = slot & 7;               // 0..7
            int gr = r0 + row;
            float4 v = make_float4(0.f, 0.f, 0.f, 0.f);
            if (gr < NN) v = *(const float4*)(X + (long)gr * F_IN + k0 + f4 * 4);
            As[row * 33 + f4 * 4 + 0] = v.x;   // scalar STS (stride 33 unaligned for .128)
            As[row * 33 + f4 * 4 + 1] = v.y;
            As[row * 33 + f4 * 4 + 2] = v.z;
            As[row * 33 + f4 * 4 + 3] = v.w;
        }
        #pragma unroll
        for (int l = 0; l < 2; l++) {
            int slot = tid + l * 256;        // 0..511 float4 slots
            int kk = slot >> 4;              // 0..31
            int cv = slot & 15;              // 0..15
            *(float4*)&Bs[kk * 64 + cv * 4] = *(const float4*)(W + (k0 + kk) * HID + cv * 4);
        }
        __syncthreads();
        #pragma unroll
        for (int kk = 0; kk < 32; kk++) {
            float4 bv = *(const float4*)&Bs[kk * 64 + tx * 4];
            #pragma unroll
            for (int i = 0; i < 8; i++) {
                float a = As[(ty * 8 + i) * 33 + kk];
                acc[i][0] += a * bv.x;
                acc[i][1] += a * bv.y;
                acc[i][2] += a * bv.z;
                acc[i][3] += a * bv.w;
            }
        }
        __syncthreads();
    }

    // write h1 + stage tile into SMEM for alpha epilogue
    float* hbuf = sm;                 // [128][65]
    #pragma unroll
    for (int i = 0; i < 8; i++) {
        int lr = ty * 8 + i;
        int gr = r0 + lr;
        #pragma unroll
        for (int j = 0; j < 4; j++) hbuf[lr * 65 + tx * 4 + j] = acc[i][j];
        if (gr < NN) {
            #pragma unroll
            for (int j = 0; j < 4; j++)
                g_h1[(long)gr * HID + tx * 4 + j] = acc[i][j];
        }
    }
    __syncthreads();

    // alphas: 128 rows x 8 heads = 1024 items, 4 per thread (scalar LDS — stride
    // 65 rows are not 16B aligned, no vector loads here)
    #pragma unroll
    for (int t = 0; t < 4; t++) {
        int item = tid + t * 256;
        int lr = item >> 3, h = item & 7;
        int gr = r0 + lr;
        if (gr < NN) {
            const float* hp = hbuf + lr * 65 + h * C1;
            float as = 0.f, ad = 0.f;
            #pragma unroll
            for (int c = 0; c < C1; c++) {
                float hv = hp[c];
                as += hv * __ldg(att_s + h * C1 + c);
                ad += hv * __ldg(att_d + h * C1 + c);
            }
            g_as1[gr * H1 + h] = as;
            g_ad1[gr * H1 + h] = ad;
        }
    }
}

// -------- layer 1 aggregation: single pass (no max shift) + elu ---------------
__global__ void k_agg1(const float* __restrict__ b1) {
    int warp = (blockIdx.x * blockDim.x + threadIdx.x) >> 5;
    int lane = threadIdx.x & 31;
    if (warp >= NN) return;
    int d = warp;
    int start = g_rowptr[d], end = g_rowptr[d + 1];
    int hid = lane & 7;
    int hA = lane >> 3;
    float ad = g_ad1[d * H1 + hid];

    float den = 0.f, acc0 = 0.f, acc1 = 0.f;
    for (int i = start; i < end; ++i) {
        int s = g_col[i];
        float e = g_as1[s * H1 + hid] + ad;
        e = (e > 0.f) ? e : NEG_SLOPE * e;
        float w = __expf(e);
        den += w;
        float wA = __shfl_sync(0xffffffffu, w, hA);
        float wB = __shfl_sync(0xffffffffu, w, hA + 4);
        const float* hr = g_h1 + (long)s * HID;
        acc0 += hr[lane] * wA;
        acc1 += hr[lane + 32] * wB;
    }
    float inv = 1.0f / den;                 // per-lane: head hid
    float iA = __shfl_sync(0xffffffffu, inv, hA);
    float iB = __shfl_sync(0xffffffffu, inv, hA + 4);
    float v0 = acc0 * iA + __ldg(b1 + lane);
    float v1 = acc1 * iB + __ldg(b1 + lane + 32);
    v0 = (v0 > 0.f) ? v0 : expm1f(v0);
    v1 = (v1 > 0.f) ? v1 : expm1f(v1);
    g_h1o[(long)d * HID + lane] = v0;
    g_h1o[(long)d * HID + lane + 32] = v1;
}

// ---------------- GEMM2 + alpha2 ----------------------------------------------
__global__ void __launch_bounds__(128) k_gemm2(
    const float* __restrict__ W2,
    const float* __restrict__ att_s2, const float* __restrict__ att_d2) {
    __shared__ float Xs[128][65];
    __shared__ float Ws[HID][NC];
    __shared__ float Sa[NC], Sd[NC];
    int tid = threadIdx.x;
    int r0 = blockIdx.x * 128;
    for (int f = tid; f < HID * NC; f += 128) Ws[f / NC][f % NC] = W2[f];
    if (tid < NC) { Sa[tid] = att_s2[tid]; Sd[tid] = att_d2[tid]; }
    for (int f = tid; f < 128 * HID; f += 128) {   // scalar stores (row stride 65)
        int rr = f >> 6, cc = f & 63;
        int gr = r0 + rr;
        Xs[rr][cc] = (gr < NN) ? g_h1o[(long)gr * HID + cc] : 0.f;
    }
    __syncthreads();
    int r = r0 + tid;
    float acc[NC];
    #pragma unroll
    for (int c = 0; c < NC; c++) acc[c] = 0.f;
    #pragma unroll 4
    for (int k = 0; k < HID; k++) {
        float xv = Xs[tid][k];
        #pragma unroll
        for (int c = 0; c < NC; c++) acc[c] += xv * Ws[k][c];
    }
    if (r < NN) {
        float a = 0.f, dd = 0.f;
        #pragma unroll
        for (int c = 0; c < NC; c++) {
            g_h2[(long)r * NC + c] = acc[c];
            a += acc[c] * Sa[c];
            dd += acc[c] * Sd[c];
        }
        g_as2[r] = a;
        g_ad2[r] = dd;
    }
}

// --------- layer 2 aggregation: single pass + log_softmax ---------------------
__global__ void k_agg2(const float* __restrict__ b2, float* __restrict__ out) {
    int warp = (blockIdx.x * blockDim.x + threadIdx.x) >> 5;
    int lane = threadIdx.x & 31;
    if (warp >= NN) return;
    int d = warp;
    int start = g_rowptr[d], end = g_rowptr[d + 1];
    float ad = g_ad2[d];

    float den = 0.f, acc0 = 0.f, acc1 = 0.f;
    for (int i = start; i < end; ++i) {
        int s = g_col[i];
        float e = g_as2[s] + ad;
        e = (e > 0.f) ? e : NEG_SLOPE * e;
        float w = __expf(e);
        den += w;
        const float* hr = g_h2 + (long)s * NC;
        acc0 += hr[lane] * w;
        if (lane < 8) acc1 += hr[lane + 32] * w;
    }
    float inv = 1.0f / den;                 // identical across lanes
    float v0 = acc0 * inv + __ldg(b2 + lane);
    float v1 = (lane < 8) ? (acc1 * inv + __ldg(b2 + lane + 32)) : -3.0e38f;

    float m = fmaxf(v0, v1);
    #pragma unroll
    for (int o = 16; o >= 1; o >>= 1) m = fmaxf(m, __shfl_xor_sync(0xffffffffu, m, o));
    float se = __expf(v0 - m) + ((lane < 8) ? __expf(v1 - m) : 0.f);
    #pragma unroll
    for (int o = 16; o >= 1; o >>= 1) se += __shfl_xor_sync(0xffffffffu, se, o);
    float lse = m + logf(se);

    out[(long)d * NC + lane] = v0 - lse;
    if (lane < 8) out[(long)d * NC + lane + 32] = v1 - lse;
}

// -----------------------------------------------------------------------------
extern "C" void kernel_launch(void* const* d_in, const int* in_sizes, int n_in,
                              void* d_out, int out_size) {
    const float* x        = (const float*)d_in[0];
    const float* W1       = (const float*)d_in[1];
    const float* att_src1 = (const float*)d_in[2];
    const float* att_dst1 = (const float*)d_in[3];
    const float* b1       = (const float*)d_in[4];
    const float* W2       = (const float*)d_in[5];
    const float* att_src2 = (const float*)d_in[6];
    const float* att_dst2 = (const float*)d_in[7];
    const float* b2       = (const float*)d_in[8];
    const void*  ei       = d_in[9];
    float* out = (float*)d_out;

    int EC = in_sizes[9] / 2;
    if (EC > E_MAX) EC = E_MAX;

    k_detect<<<1, 1024>>>(ei, EC);
    k_zero_deg<<<(NN + 255) / 256, 256>>>();
    k_hist<<<(EC + 255) / 256, 256>>>(ei, EC);
    int nblocks = (NN + 1023) / 1024;
    k_scan_block<<<nblocks, 1024>>>();
    k_scan_tops<<<1, 32>>>(nblocks);
    k_scan_fix<<<nblocks, 1024>>>(EC);
    k_scatter<<<(EC + 255) / 256, 256>>>(ei, EC);

    k_gemm1<<<(NN + 127) / 128, 256>>>(x, W1, att_src1, att_dst1);
    k_agg1<<<(NN * 32 + 255) / 256, 256>>>(b1);

    k_gemm2<<<(NN + 127) / 128, 128>>>(W2, att_src2, att_dst2);
    k_agg2<<<(NN * 32 + 255) / 256, 256>>>(b2, out);
}

// round 5
// speedup vs baseline: 1.1453x; 1.0035x over previous
#include <cuda_runtime.h>
#include <cuda_bf16.h>
#include <math.h>

#define NN      100000
#define F_IN    256
#define HID     64
#define H1      8
#define C1      8
#define NC      40
#define E_MAX   1700000
#define NEG_SLOPE 0.2f
#define AST     132     // transposed-A tile row stride (floats), even -> 8B pairs

// ---------------- packed f32x2 helpers ----------------------------------------
__device__ __forceinline__ unsigned long long ffma2(
    unsigned long long a, unsigned long long b, unsigned long long c) {
    unsigned long long d;
    asm("fma.rn.f32x2 %0, %1, %2, %3;" : "=l"(d) : "l"(a), "l"(b), "l"(c));
    return d;
}
__device__ __forceinline__ unsigned long long pack2(float lo, float hi) {
    unsigned long long d;
    asm("mov.b64 %0, {%1, %2};" : "=l"(d) : "f"(lo), "f"(hi));
    return d;
}
__device__ __forceinline__ void unpack2(unsigned long long v, float& lo, float& hi) {
    asm("mov.b64 {%0, %1}, %2;" : "=f"(lo), "=f"(hi) : "l"(v));
}

// ---------------- scratch -----------------------------------------------------
__device__ int   g_is64;
__device__ int   g_deg[NN];
__device__ int   g_rowptr[NN + 1];
__device__ int   g_fill[NN];
__device__ int   g_col[E_MAX];
__device__ int   g_bsum[256];
__device__ float g_h1[(long)NN * HID];
__device__ float g_as1[NN * H1];
__device__ float g_ad1[NN * H1];
__device__ float g_h1o[(long)NN * HID];
__device__ float g_h2[(long)NN * NC];
__device__ float g_as2[NN];
__device__ float g_ad2[NN];

// ---------------- edge dtype handling ----------------------------------------
__global__ void k_detect(const void* ei, int EC) {
    __shared__ int bad;
    if (threadIdx.x == 0) bad = 0;
    __syncthreads();
    const long long* p = (const long long*)ei;
    int n = EC < 1024 ? EC : 1024;
    if ((int)threadIdx.x < n) {
        long long v = p[threadIdx.x];
        if (v < 0 || v >= NN) atomicExch(&bad, 1);
    }
    __syncthreads();
    if (threadIdx.x == 0) g_is64 = bad ? 0 : 1;
}

__device__ __forceinline__ int edge_at(const void* ei, int idx) {
    return g_is64 ? (int)((const long long*)ei)[idx] : ((const int*)ei)[idx];
}

// ---------------- CSR build ---------------------------------------------------
__global__ void k_zero_deg() {
    int i = blockIdx.x * blockDim.x + threadIdx.x;
    if (i < NN) g_deg[i] = 0;
}

__global__ void k_hist(const void* ei, int EC) {
    int i = blockIdx.x * blockDim.x + threadIdx.x;
    if (i < EC) {
        int d = edge_at(ei, EC + i);
        if (d >= 0 && d < NN) atomicAdd(&g_deg[d], 1);
    }
}

__global__ void k_scan_block() {
    __shared__ int ws[32];
    int tid = threadIdx.x;
    int gid = blockIdx.x * 1024 + tid;
    int v = (gid < NN) ? g_deg[gid] : 0;
    int x = v;
    #pragma unroll
    for (int o = 1; o < 32; o <<= 1) {
        int t = __shfl_up_sync(0xffffffffu, x, o);
        if ((tid & 31) >= o) x += t;
    }
    if ((tid & 31) == 31) ws[tid >> 5] = x;
    __syncthreads();
    if (tid < 32) {
        int w = ws[tid];
        int y = w;
        #pragma unroll
        for (int o = 1; o < 32; o <<= 1) {
            int t = __shfl_up_sync(0xffffffffu, y, o);
            if (tid >= o) y += t;
        }
        ws[tid] = y - w;
    }
    __syncthreads();
    int incl = x + ws[tid >> 5];
    if (gid < NN) g_rowptr[gid] = incl - v;
    if (tid == 1023) g_bsum[blockIdx.x] = incl;
}

__global__ void k_scan_tops(int nblocks) {
    if (threadIdx.x == 0 && blockIdx.x == 0) {
        int run = 0;
        for (int b = 0; b < nblocks; b++) {
            int t = g_bsum[b];
            g_bsum[b] = run;
            run += t;
        }
    }
}

__global__ void k_scan_fix(int EC) {
    int gid = blockIdx.x * 1024 + threadIdx.x;
    if (gid < NN) {
        int v = g_rowptr[gid] + g_bsum[gid >> 10];
        g_rowptr[gid] = v;
        g_fill[gid] = v;
    }
    if (gid == 0) g_rowptr[NN] = EC;
}

__global__ void k_scatter(const void* ei, int EC) {
    int i = blockIdx.x * blockDim.x + threadIdx.x;
    if (i < EC) {
        int s = edge_at(ei, i);
        int d = edge_at(ei, EC + i);
        if (d >= 0 && d < NN) {
            int p = atomicAdd(&g_fill[d], 1);
            if (p >= 0 && p < E_MAX) g_col[p] = s;
        }
    }
}

// ------- GEMM1 (128x64 tile, FFMA2 inner) + fused alpha epilogue --------------
__global__ void __launch_bounds__(256) k_gemm1(
    const float* __restrict__ X, const float* __restrict__ W,
    const float* __restrict__ att_s, const float* __restrict__ att_d) {
    __shared__ __align__(16) float sm[128 * 65];  // Ast[32][AST] + Bs[32][64]; hbuf in epilogue
    float* Ast = sm;                  // transposed: [kk][row], stride AST=132
    float* Bs  = sm + 32 * AST;       // [32][64]; base 4224 floats -> 16B aligned
    int tid = threadIdx.x;
    int r0 = blockIdx.x * 128;
    int tx = tid & 15, ty = tid >> 4;

    unsigned long long acc2[4][4];    // [row-pair p][col c] = rows (ty*8+2p, +1)
    unsigned long long z = pack2(0.f, 0.f);
    #pragma unroll
    for (int p = 0; p < 4; p++)
        #pragma unroll
        for (int c = 0; c < 4; c++) acc2[p][c] = z;

    for (int k0 = 0; k0 < F_IN; k0 += 32) {
        #pragma unroll
        for (int l = 0; l < 4; l++) {
            int slot = tid + l * 256;        // 0..1023 float4 slots
            int row = slot >> 3;             // 0..127
            int f4 = slot & 7;               // 0..7
            int gr = r0 + row;
            float4 v = make_float4(0.f, 0.f, 0.f, 0.f);
            if (gr < NN) v = *(const float4*)(X + (long)gr * F_IN + k0 + f4 * 4);
            Ast[(f4 * 4 + 0) * AST + row] = v.x;   // transposed scalar STS
            Ast[(f4 * 4 + 1) * AST + row] = v.y;
            Ast[(f4 * 4 + 2) * AST + row] = v.z;
            Ast[(f4 * 4 + 3) * AST + row] = v.w;
        }
        #pragma unroll
        for (int l = 0; l < 2; l++) {
            int slot = tid + l * 256;        // 0..511 float4 slots
            int kk = slot >> 4;              // 0..31
            int cv = slot & 15;              // 0..15
            *(float4*)&Bs[kk * 64 + cv * 4] = *(const float4*)(W + (k0 + kk) * HID + cv * 4);
        }
        __syncthreads();
        #pragma unroll
        for (int kk = 0; kk < 32; kk++) {
            float4 bv = *(const float4*)&Bs[kk * 64 + tx * 4];
            unsigned long long br[4];
            br[0] = pack2(bv.x, bv.x);
            br[1] = pack2(bv.y, bv.y);
            br[2] = pack2(bv.z, bv.z);
            br[3] = pack2(bv.w, bv.w);
            const float* ab = Ast + kk * AST + ty * 8;
            #pragma unroll
            for (int p = 0; p < 4; p++) {
                unsigned long long ap = *(const unsigned long long*)(ab + 2 * p);
                acc2[p][0] = ffma2(ap, br[0], acc2[p][0]);
                acc2[p][1] = ffma2(ap, br[1], acc2[p][1]);
                acc2[p][2] = ffma2(ap, br[2], acc2[p][2]);
                acc2[p][3] = ffma2(ap, br[3], acc2[p][3]);
            }
        }
        __syncthreads();
    }

    // unpack, write h1 + stage tile into SMEM for alpha epilogue
    float* hbuf = sm;                 // [128][65]
    #pragma unroll
    for (int p = 0; p < 4; p++) {
        float lo[4], hi[4];
        #pragma unroll
        for (int c = 0; c < 4; c++) unpack2(acc2[p][c], lo[c], hi[c]);
        int lr = ty * 8 + 2 * p;
        int gr = r0 + lr;
        #pragma unroll
        for (int c = 0; c < 4; c++) {
            hbuf[lr * 65 + tx * 4 + c] = lo[c];
            hbuf[(lr + 1) * 65 + tx * 4 + c] = hi[c];
        }
        if (gr < NN) {
            #pragma unroll
            for (int c = 0; c < 4; c++)
                g_h1[(long)gr * HID + tx * 4 + c] = lo[c];
        }
        if (gr + 1 < NN) {
            #pragma unroll
            for (int c = 0; c < 4; c++)
                g_h1[(long)(gr + 1) * HID + tx * 4 + c] = hi[c];
        }
    }
    __syncthreads();

    // alphas: 128 rows x 8 heads = 1024 items, 4 per thread (scalar LDS)
    #pragma unroll
    for (int t = 0; t < 4; t++) {
        int item = tid + t * 256;
        int lr = item >> 3, h = item & 7;
        int gr = r0 + lr;
        if (gr < NN) {
            const float* hp = hbuf + lr * 65 + h * C1;
            float as = 0.f, ad = 0.f;
            #pragma unroll
            for (int c = 0; c < C1; c++) {
                float hv = hp[c];
                as += hv * __ldg(att_s + h * C1 + c);
                ad += hv * __ldg(att_d + h * C1 + c);
            }
            g_as1[gr * H1 + h] = as;
            g_ad1[gr * H1 + h] = ad;
        }
    }
}

// -------- layer 1 aggregation: single pass + elu ------------------------------
__global__ void k_agg1(const float* __restrict__ b1) {
    int warp = (blockIdx.x * blockDim.x + threadIdx.x) >> 5;
    int lane = threadIdx.x & 31;
    if (warp >= NN) return;
    int d = warp;
    int start = g_rowptr[d], end = g_rowptr[d + 1];
    int hid = lane & 7;
    int hA = lane >> 3;
    float ad = g_ad1[d * H1 + hid];

    float den = 0.f, acc0 = 0.f, acc1 = 0.f;
    for (int i = start; i < end; ++i) {
        int s = g_col[i];
        float e = g_as1[s * H1 + hid] + ad;
        e = (e > 0.f) ? e : NEG_SLOPE * e;
        float w = __expf(e);
        den += w;
        float wA = __shfl_sync(0xffffffffu, w, hA);
        float wB = __shfl_sync(0xffffffffu, w, hA + 4);
        const float* hr = g_h1 + (long)s * HID;
        acc0 += hr[lane] * wA;
        acc1 += hr[lane + 32] * wB;
    }
    float inv = 1.0f / den;
    float iA = __shfl_sync(0xffffffffu, inv, hA);
    float iB = __shfl_sync(0xffffffffu, inv, hA + 4);
    float v0 = acc0 * iA + __ldg(b1 + lane);
    float v1 = acc1 * iB + __ldg(b1 + lane + 32);
    v0 = (v0 > 0.f) ? v0 : expm1f(v0);
    v1 = (v1 > 0.f) ? v1 : expm1f(v1);
    g_h1o[(long)d * HID + lane] = v0;
    g_h1o[(long)d * HID + lane + 32] = v1;
}

// ---------------- GEMM2 (FFMA2 inner) + alpha2 --------------------------------
__global__ void __launch_bounds__(128) k_gemm2(
    const float* __restrict__ W2,
    const float* __restrict__ att_s2, const float* __restrict__ att_d2) {
    __shared__ __align__(16) float Xs[128][65];
    __shared__ __align__(16) float Ws[HID][NC];   // row stride 40 (even) -> 8B pairs
    __shared__ float Sa[NC], Sd[NC];
    int tid = threadIdx.x;
    int r0 = blockIdx.x * 128;
    for (int f = tid; f < HID * NC; f += 128) Ws[f / NC][f % NC] = W2[f];
    if (tid < NC) { Sa[tid] = att_s2[tid]; Sd[tid] = att_d2[tid]; }
    for (int f = tid; f < 128 * HID; f += 128) {
        int rr = f >> 6, cc = f & 63;
        int gr = r0 + rr;
        Xs[rr][cc] = (gr < NN) ? g_h1o[(long)gr * HID + cc] : 0.f;
    }
    __syncthreads();
    int r = r0 + tid;
    unsigned long long acc2[NC / 2];
    unsigned long long z = pack2(0.f, 0.f);
    #pragma unroll
    for (int c = 0; c < NC / 2; c++) acc2[c] = z;
    #pragma unroll 4
    for (int k = 0; k < HID; k++) {
        float xv = Xs[tid][k];
        unsigned long long xp = pack2(xv, xv);
        const unsigned long long* wp = (const unsigned long long*)&Ws[k][0];  // broadcast
        #pragma unroll
        for (int c = 0; c < NC / 2; c++) acc2[c] = ffma2(xp, wp[c], acc2[c]);
    }
    if (r < NN) {
        float a = 0.f, dd = 0.f;
        #pragma unroll
        for (int c = 0; c < NC / 2; c++) {
            float lo, hi;
            unpack2(acc2[c], lo, hi);
            g_h2[(long)r * NC + 2 * c]     = lo;
            g_h2[(long)r * NC + 2 * c + 1] = hi;
            a  += lo * Sa[2 * c] + hi * Sa[2 * c + 1];
            dd += lo * Sd[2 * c] + hi * Sd[2 * c + 1];
        }
        g_as2[r] = a;
        g_ad2[r] = dd;
    }
}

// --------- layer 2 aggregation: single pass + log_softmax ---------------------
__global__ void k_agg2(const float* __restrict__ b2, float* __restrict__ out) {
    int warp = (blockIdx.x * blockDim.x + threadIdx.x) >> 5;
    int lane = threadIdx.x & 31;
    if (warp >= NN) return;
    int d = warp;
    int start = g_rowptr[d], end = g_rowptr[d + 1];
    float ad = g_ad2[d];

    float den = 0.f, acc0 = 0.f, acc1 = 0.f;
    for (int i = start; i < end; ++i) {
        int s = g_col[i];
        float e = g_as2[s] + ad;
        e = (e > 0.f) ? e : NEG_SLOPE * e;
        float w = __expf(e);
        den += w;
        const float* hr = g_h2 + (long)s * NC;
        acc0 += hr[lane] * w;
        if (lane < 8) acc1 += hr[lane + 32] * w;
    }
    float inv = 1.0f / den;
    float v0 = acc0 * inv + __ldg(b2 + lane);
    float v1 = (lane < 8) ? (acc1 * inv + __ldg(b2 + lane + 32)) : -3.0e38f;

    float m = fmaxf(v0, v1);
    #pragma unroll
    for (int o = 16; o >= 1; o >>= 1) m = fmaxf(m, __shfl_xor_sync(0xffffffffu, m, o));
    float se = __expf(v0 - m) + ((lane < 8) ? __expf(v1 - m) : 0.f);
    #pragma unroll
    for (int o = 16; o >= 1; o >>= 1) se += __shfl_xor_sync(0xffffffffu, se, o);
    float lse = m + logf(se);

    out[(long)d * NC + lane] = v0 - lse;
    if (lane < 8) out[(long)d * NC + lane + 32] = v1 - lse;
}

// -----------------------------------------------------------------------------
extern "C" void kernel_launch(void* const* d_in, const int* in_sizes, int n_in,
                              void* d_out, int out_size) {
    const float* x        = (const float*)d_in[0];
    const float* W1       = (const float*)d_in[1];
    const float* att_src1 = (const float*)d_in[2];
    const float* att_dst1 = (const float*)d_in[3];
    const float* b1       = (const float*)d_in[4];
    const float* W2       = (const float*)d_in[5];
    const float* att_src2 = (const float*)d_in[6];
    const float* att_dst2 = (const float*)d_in[7];
    const float* b2       = (const float*)d_in[8];
    const void*  ei       = d_in[9];
    float* out = (float*)d_out;

    int EC = in_sizes[9] / 2;
    if (EC > E_MAX) EC = E_MAX;

    k_detect<<<1, 1024>>>(ei, EC);
    k_zero_deg<<<(NN + 255) / 256, 256>>>();
    k_hist<<<(EC + 255) / 256, 256>>>(ei, EC);
    int nblocks = (NN + 1023) / 1024;
    k_scan_block<<<nblocks, 1024>>>();
    k_scan_tops<<<1, 32>>>(nblocks);
    k_scan_fix<<<nblocks, 1024>>>(EC);
    k_scatter<<<(EC + 255) / 256, 256>>>(ei, EC);

    k_gemm1<<<(NN + 127) / 128, 256>>>(x, W1, att_src1, att_dst1);
    k_agg1<<<(NN * 32 + 255) / 256, 256>>>(b1);

    k_gemm2<<<(NN + 127) / 128, 128>>>(W2, att_src2, att_dst2);
    k_agg2<<<(NN * 32 + 255) / 256, 256>>>(b2, out);
}

// round 6
// speedup vs baseline: 1.1720x; 1.0233x over previous
#include <cuda_runtime.h>
#include <cuda_bf16.h>
#include <math.h>

#define NN      100000
#define F_IN    256
#define HID     64
#define H1      8
#define C1      8
#define NC      40
#define E_MAX   1700000
#define NEG_SLOPE 0.2f
#define AST     132

// ---------------- packed f32x2 helpers ----------------------------------------
__device__ __forceinline__ unsigned long long ffma2(
    unsigned long long a, unsigned long long b, unsigned long long c) {
    unsigned long long d;
    asm("fma.rn.f32x2 %0, %1, %2, %3;" : "=l"(d) : "l"(a), "l"(b), "l"(c));
    return d;
}
__device__ __forceinline__ unsigned long long pack2(float lo, float hi) {
    unsigned long long d;
    asm("mov.b64 %0, {%1, %2};" : "=l"(d) : "f"(lo), "f"(hi));
    return d;
}
__device__ __forceinline__ void unpack2(unsigned long long v, float& lo, float& hi) {
    asm("mov.b64 {%0, %1}, %2;" : "=f"(lo), "=f"(hi) : "l"(v));
}

// ---------------- scratch -----------------------------------------------------
__device__ int   g_is64;
__device__ int   g_deg[NN];
__device__ int   g_rowptr[NN + 1];
__device__ int   g_fill[NN];
__device__ int   g_col[E_MAX];
__device__ int   g_bsum[256];
__device__ float g_h1[(long)NN * HID];
__device__ float g_as1[NN * H1];
__device__ float g_ad1[NN * H1];
__device__ float g_h1o[(long)NN * HID];
__device__ float g_h2[(long)NN * NC];
__device__ float g_as2[NN];
__device__ float g_ad2[NN];

// -------- init: zero degrees + edge dtype detection (block 0) -----------------
__global__ void k_init(const void* ei, int EC) {
    int i = blockIdx.x * blockDim.x + threadIdx.x;
    if (i < NN) g_deg[i] = 0;
    if (blockIdx.x == 0) {
        __shared__ int bad;
        if (threadIdx.x == 0) bad = 0;
        __syncthreads();
        const long long* p = (const long long*)ei;
        int n = EC < 256 ? EC : 256;
        if ((int)threadIdx.x < n) {
            long long v = p[threadIdx.x];
            if (v < 0 || v >= NN) atomicExch(&bad, 1);
        }
        __syncthreads();
        if (threadIdx.x == 0) g_is64 = bad ? 0 : 1;
    }
}

__device__ __forceinline__ int edge_at(const void* ei, int idx) {
    return g_is64 ? (int)((const long long*)ei)[idx] : ((const int*)ei)[idx];
}

// ---------------- CSR build ---------------------------------------------------
__global__ void k_hist(const void* ei, int EC) {
    int i = blockIdx.x * blockDim.x + threadIdx.x;
    if (i < EC) {
        int d = edge_at(ei, EC + i);
        if (d >= 0 && d < NN) atomicAdd(&g_deg[d], 1);
    }
}

__global__ void k_scan_block() {
    __shared__ int ws[32];
    int tid = threadIdx.x;
    int gid = blockIdx.x * 1024 + tid;
    int v = (gid < NN) ? g_deg[gid] : 0;
    int x = v;
    #pragma unroll
    for (int o = 1; o < 32; o <<= 1) {
        int t = __shfl_up_sync(0xffffffffu, x, o);
        if ((tid & 31) >= o) x += t;
    }
    if ((tid & 31) == 31) ws[tid >> 5] = x;
    __syncthreads();
    if (tid < 32) {
        int w = ws[tid];
        int y = w;
        #pragma unroll
        for (int o = 1; o < 32; o <<= 1) {
            int t = __shfl_up_sync(0xffffffffu, y, o);
            if (tid >= o) y += t;
        }
        ws[tid] = y - w;
    }
    __syncthreads();
    int incl = x + ws[tid >> 5];
    if (gid < NN) g_rowptr[gid] = incl - v;
    if (tid == 1023) g_bsum[blockIdx.x] = incl;
}

// single warp, chunked shfl scan (exclusive) of block sums
__global__ void k_scan_tops(int nblocks) {
    int lane = threadIdx.x;
    int run = 0;
    for (int base = 0; base < nblocks; base += 32) {
        int idx = base + lane;
        int v = (idx < nblocks) ? g_bsum[idx] : 0;
        int x = v;
        #pragma unroll
        for (int o = 1; o < 32; o <<= 1) {
            int t = __shfl_up_sync(0xffffffffu, x, o);
            if (lane >= o) x += t;
        }
        if (idx < nblocks) g_bsum[idx] = run + x - v;
        run += __shfl_sync(0xffffffffu, x, 31);
    }
}

__global__ void k_scan_fix(int EC) {
    int gid = blockIdx.x * 1024 + threadIdx.x;
    if (gid < NN) {
        int v = g_rowptr[gid] + g_bsum[gid >> 10];
        g_rowptr[gid] = v;
        g_fill[gid] = v;
    }
    if (gid == 0) g_rowptr[NN] = EC;
}

__global__ void k_scatter(const void* ei, int EC) {
    int i = blockIdx.x * blockDim.x + threadIdx.x;
    if (i < EC) {
        int s = edge_at(ei, i);
        int d = edge_at(ei, EC + i);
        if (d >= 0 && d < NN) {
            int p = atomicAdd(&g_fill[d], 1);
            if (p >= 0 && p < E_MAX) g_col[p] = s;
        }
    }
}

// ------- GEMM1 (128x64 tile, FFMA2 inner) + fused alpha epilogue --------------
__global__ void __launch_bounds__(256) k_gemm1(
    const float* __restrict__ X, const float* __restrict__ W,
    const float* __restrict__ att_s, const float* __restrict__ att_d) {
    __shared__ __align__(16) float sm[128 * 65];
    float* Ast = sm;                  // transposed: [kk][row], stride AST=132
    float* Bs  = sm + 32 * AST;
    int tid = threadIdx.x;
    int r0 = blockIdx.x * 128;
    int tx = tid & 15, ty = tid >> 4;

    unsigned long long acc2[4][4];
    unsigned long long z = pack2(0.f, 0.f);
    #pragma unroll
    for (int p = 0; p < 4; p++)
        #pragma unroll
        for (int c = 0; c < 4; c++) acc2[p][c] = z;

    for (int k0 = 0; k0 < F_IN; k0 += 32) {
        #pragma unroll
        for (int l = 0; l < 4; l++) {
            int slot = tid + l * 256;
            int row = slot >> 3;
            int f4 = slot & 7;
            int gr = r0 + row;
            float4 v = make_float4(0.f, 0.f, 0.f, 0.f);
            if (gr < NN) v = *(const float4*)(X + (long)gr * F_IN + k0 + f4 * 4);
            Ast[(f4 * 4 + 0) * AST + row] = v.x;
            Ast[(f4 * 4 + 1) * AST + row] = v.y;
            Ast[(f4 * 4 + 2) * AST + row] = v.z;
            Ast[(f4 * 4 + 3) * AST + row] = v.w;
        }
        #pragma unroll
        for (int l = 0; l < 2; l++) {
            int slot = tid + l * 256;
            int kk = slot >> 4;
            int cv = slot & 15;
            *(float4*)&Bs[kk * 64 + cv * 4] = *(const float4*)(W + (k0 + kk) * HID + cv * 4);
        }
        __syncthreads();
        #pragma unroll
        for (int kk = 0; kk < 32; kk++) {
            float4 bv = *(const float4*)&Bs[kk * 64 + tx * 4];
            unsigned long long br[4];
            br[0] = pack2(bv.x, bv.x);
            br[1] = pack2(bv.y, bv.y);
            br[2] = pack2(bv.z, bv.z);
            br[3] = pack2(bv.w, bv.w);
            const float* ab = Ast + kk * AST + ty * 8;
            #pragma unroll
            for (int p = 0; p < 4; p++) {
                unsigned long long ap = *(const unsigned long long*)(ab + 2 * p);
                acc2[p][0] = ffma2(ap, br[0], acc2[p][0]);
                acc2[p][1] = ffma2(ap, br[1], acc2[p][1]);
                acc2[p][2] = ffma2(ap, br[2], acc2[p][2]);
                acc2[p][3] = ffma2(ap, br[3], acc2[p][3]);
            }
        }
        __syncthreads();
    }

    float* hbuf = sm;                 // [128][65]
    #pragma unroll
    for (int p = 0; p < 4; p++) {
        float lo[4], hi[4];
        #pragma unroll
        for (int c = 0; c < 4; c++) unpack2(acc2[p][c], lo[c], hi[c]);
        int lr = ty * 8 + 2 * p;
        int gr = r0 + lr;
        #pragma unroll
        for (int c = 0; c < 4; c++) {
            hbuf[lr * 65 + tx * 4 + c] = lo[c];
            hbuf[(lr + 1) * 65 + tx * 4 + c] = hi[c];
        }
        if (gr < NN) {
            #pragma unroll
            for (int c = 0; c < 4; c++)
                g_h1[(long)gr * HID + tx * 4 + c] = lo[c];
        }
        if (gr + 1 < NN) {
            #pragma unroll
            for (int c = 0; c < 4; c++)
                g_h1[(long)(gr + 1) * HID + tx * 4 + c] = hi[c];
        }
    }
    __syncthreads();

    #pragma unroll
    for (int t = 0; t < 4; t++) {
        int item = tid + t * 256;
        int lr = item >> 3, h = item & 7;
        int gr = r0 + lr;
        if (gr < NN) {
            const float* hp = hbuf + lr * 65 + h * C1;
            float as = 0.f, ad = 0.f;
            #pragma unroll
            for (int c = 0; c < C1; c++) {
                float hv = hp[c];
                as += hv * __ldg(att_s + h * C1 + c);
                ad += hv * __ldg(att_d + h * C1 + c);
            }
            g_as1[gr * H1 + h] = as;
            g_ad1[gr * H1 + h] = ad;
        }
    }
}

// -------- layer 1 aggregation: float2 per lane, single pass + elu -------------
__global__ void k_agg1(const float* __restrict__ b1) {
    int warp = (blockIdx.x * blockDim.x + threadIdx.x) >> 5;
    int lane = threadIdx.x & 31;
    if (warp >= NN) return;
    int d = warp;
    int start = g_rowptr[d], end = g_rowptr[d + 1];
    int hid = lane & 7;           // head this lane evaluates attention for
    int wsrc = lane >> 2;         // lane holding the weight for channel pair (2l,2l+1)
    float ad = g_ad1[d * H1 + hid];

    unsigned long long acc = pack2(0.f, 0.f);
    float den = 0.f;
    #pragma unroll 2
    for (int i = start; i < end; ++i) {
        int s = g_col[i];
        float e = g_as1[s * H1 + hid] + ad;
        e = (e > 0.f) ? e : NEG_SLOPE * e;
        float w = __expf(e);
        den += w;
        float wl = __shfl_sync(0xffffffffu, w, wsrc);
        unsigned long long hv = *(const unsigned long long*)(g_h1 + (long)s * HID + 2 * lane);
        acc = ffma2(hv, pack2(wl, wl), acc);
    }
    float inv = 1.0f / den;
    float il = __shfl_sync(0xffffffffu, inv, wsrc);
    float lo, hi;
    unpack2(acc, lo, hi);
    float v0 = lo * il + __ldg(b1 + 2 * lane);
    float v1 = hi * il + __ldg(b1 + 2 * lane + 1);
    v0 = (v0 > 0.f) ? v0 : expm1f(v0);
    v1 = (v1 > 0.f) ? v1 : expm1f(v1);
    *(float2*)(g_h1o + (long)d * HID + 2 * lane) = make_float2(v0, v1);
}

// ---------------- GEMM2 (FFMA2 inner) + alpha2 --------------------------------
__global__ void __launch_bounds__(128) k_gemm2(
    const float* __restrict__ W2,
    const float* __restrict__ att_s2, const float* __restrict__ att_d2) {
    __shared__ __align__(16) float Xs[128][65];
    __shared__ __align__(16) float Ws[HID][NC];
    __shared__ float Sa[NC], Sd[NC];
    int tid = threadIdx.x;
    int r0 = blockIdx.x * 128;
    for (int f = tid; f < HID * NC; f += 128) Ws[f / NC][f % NC] = W2[f];
    if (tid < NC) { Sa[tid] = att_s2[tid]; Sd[tid] = att_d2[tid]; }
    for (int f = tid; f < 128 * HID; f += 128) {
        int rr = f >> 6, cc = f & 63;
        int gr = r0 + rr;
        Xs[rr][cc] = (gr < NN) ? g_h1o[(long)gr * HID + cc] : 0.f;
    }
    __syncthreads();
    int r = r0 + tid;
    unsigned long long acc2[NC / 2];
    unsigned long long z = pack2(0.f, 0.f);
    #pragma unroll
    for (int c = 0; c < NC / 2; c++) acc2[c] = z;
    #pragma unroll 4
    for (int k = 0; k < HID; k++) {
        float xv = Xs[tid][k];
        unsigned long long xp = pack2(xv, xv);
        const unsigned long long* wp = (const unsigned long long*)&Ws[k][0];
        #pragma unroll
        for (int c = 0; c < NC / 2; c++) acc2[c] = ffma2(xp, wp[c], acc2[c]);
    }
    if (r < NN) {
        float a = 0.f, dd = 0.f;
        #pragma unroll
        for (int c = 0; c < NC / 2; c++) {
            float lo, hi;
            unpack2(acc2[c], lo, hi);
            g_h2[(long)r * NC + 2 * c]     = lo;
            g_h2[(long)r * NC + 2 * c + 1] = hi;
            a  += lo * Sa[2 * c] + hi * Sa[2 * c + 1];
            dd += lo * Sd[2 * c] + hi * Sd[2 * c + 1];
        }
        g_as2[r] = a;
        g_ad2[r] = dd;
    }
}

// --------- layer 2 aggregation: float2 lanes, single pass + log_softmax -------
__global__ void k_agg2(const float* __restrict__ b2, float* __restrict__ out) {
    int warp = (blockIdx.x * blockDim.x + threadIdx.x) >> 5;
    int lane = threadIdx.x & 31;
    if (warp >= NN) return;
    int d = warp;
    int start = g_rowptr[d], end = g_rowptr[d + 1];
    float ad = g_ad2[d];
    bool act = lane < 20;         // 20 lanes x 2 channels = 40

    unsigned long long acc = pack2(0.f, 0.f);
    float den = 0.f;
    #pragma unroll 2
    for (int i = start; i < end; ++i) {
        int s = g_col[i];
        float e = g_as2[s] + ad;
        e = (e > 0.f) ? e : NEG_SLOPE * e;
        float w = __expf(e);
        den += w;
        if (act) {
            unsigned long long hv = *(const unsigned long long*)(g_h2 + (long)s * NC + 2 * lane);
            acc = ffma2(hv, pack2(w, w), acc);
        }
    }
    float inv = 1.0f / den;
    float lo, hi;
    unpack2(acc, lo, hi);
    float v0 = act ? (lo * inv + __ldg(b2 + 2 * lane))     : -3.0e38f;
    float v1 = act ? (hi * inv + __ldg(b2 + 2 * lane + 1)) : -3.0e38f;

    float m = fmaxf(v0, v1);
    #pragma unroll
    for (int o = 16; o >= 1; o >>= 1) m = fmaxf(m, __shfl_xor_sync(0xffffffffu, m, o));
    float se = act ? (__expf(v0 - m) + __expf(v1 - m)) : 0.f;
    #pragma unroll
    for (int o = 16; o >= 1; o >>= 1) se += __shfl_xor_sync(0xffffffffu, se, o);
    float lse = m + logf(se);

    if (act)
        *(float2*)(out + (long)d * NC + 2 * lane) = make_float2(v0 - lse, v1 - lse);
}

// -----------------------------------------------------------------------------
extern "C" void kernel_launch(void* const* d_in, const int* in_sizes, int n_in,
                              void* d_out, int out_size) {
    const float* x        = (const float*)d_in[0];
    const float* W1       = (const float*)d_in[1];
    const float* att_src1 = (const float*)d_in[2];
    const float* att_dst1 = (const float*)d_in[3];
    const float* b1       = (const float*)d_in[4];
    const float* W2       = (const float*)d_in[5];
    const float* att_src2 = (const float*)d_in[6];
    const float* att_dst2 = (const float*)d_in[7];
    const float* b2       = (const float*)d_in[8];
    const void*  ei       = d_in[9];
    float* out = (float*)d_out;

    int EC = in_sizes[9] / 2;
    if (EC > E_MAX) EC = E_MAX;
    int nblocks = (NN + 1023) / 1024;

    // fork: gemm1 (independent of CSR) runs on a side stream concurrently
    cudaStream_t side;
    cudaStreamCreateWithFlags(&side, cudaStreamNonBlocking);
    cudaEvent_t evFork, evJoin;
    cudaEventCreateWithFlags(&evFork, cudaEventDisableTiming);
    cudaEventCreateWithFlags(&evJoin, cudaEventDisableTiming);

    cudaEventRecord(evFork, 0);
    cudaStreamWaitEvent(side, evFork, 0);
    k_gemm1<<<(NN + 127) / 128, 256, 0, side>>>(x, W1, att_src1, att_dst1);
    cudaEventRecord(evJoin, side);

    // main stream: CSR build
    k_init<<<(NN + 255) / 256, 256>>>(ei, EC);
    k_hist<<<(EC + 255) / 256, 256>>>(ei, EC);
    k_scan_block<<<nblocks, 1024>>>();
    k_scan_tops<<<1, 32>>>(nblocks);
    k_scan_fix<<<nblocks, 1024>>>(EC);
    k_scatter<<<(EC + 255) / 256, 256>>>(ei, EC);

    // join, then the dependent tail
    cudaStreamWaitEvent(0, evJoin, 0);
    k_agg1<<<(NN * 32 + 255) / 256, 256>>>(b1);
    k_gemm2<<<(NN + 127) / 128, 128>>>(W2, att_src2, att_dst2);
    k_agg2<<<(NN * 32 + 255) / 256, 256>>>(b2, out);
    // streams/events intentionally not destroyed mid-capture (bounded: a few
    // kernel_launch invocations per run; graph replays do not re-enter here)
}

// round 7
// speedup vs baseline: 1.3689x; 1.1681x over previous
#include <cuda_runtime.h>
#include <cuda_bf16.h>
#include <math.h>

#define NN      100000
#define F_IN    256
#define HID     64
#define H1      8
#define C1      8
#define NC      40
#define E_MAX   1700000
#define NEG_SLOPE 0.2f
#define AST     132

// ---------------- packed f32x2 helpers ----------------------------------------
__device__ __forceinline__ unsigned long long ffma2(
    unsigned long long a, unsigned long long b, unsigned long long c) {
    unsigned long long d;
    asm("fma.rn.f32x2 %0, %1, %2, %3;" : "=l"(d) : "l"(a), "l"(b), "l"(c));
    return d;
}
__device__ __forceinline__ unsigned long long pack2(float lo, float hi) {
    unsigned long long d;
    asm("mov.b64 %0, {%1, %2};" : "=l"(d) : "f"(lo), "f"(hi));
    return d;
}
__device__ __forceinline__ void unpack2(unsigned long long v, float& lo, float& hi) {
    asm("mov.b64 {%0, %1}, %2;" : "=f"(lo), "=f"(hi) : "l"(v));
}

// ---------------- scratch -----------------------------------------------------
__device__ int   g_is64;
__device__ int   g_deg[NN];
__device__ int   g_rowptr[NN + 1];
__device__ int   g_fill[NN];
__device__ int   g_col[E_MAX];
__device__ int   g_bsum[256];
__device__ float g_h1[(long)NN * HID];
__device__ float g_as1[NN * H1];
__device__ float g_ad1[NN * H1];
__device__ float g_h1o[(long)NN * HID];
__device__ float g_h2[(long)NN * NC];
__device__ float g_as2[NN];
__device__ float g_ad2[NN];

// -------- init: zero degrees + edge dtype detection (block 0) -----------------
__global__ void k_init(const void* ei, int EC) {
    int i = blockIdx.x * blockDim.x + threadIdx.x;
    if (i < NN) g_deg[i] = 0;
    if (blockIdx.x == 0) {
        __shared__ int bad;
        if (threadIdx.x == 0) bad = 0;
        __syncthreads();
        const long long* p = (const long long*)ei;
        int n = EC < 256 ? EC : 256;
        if ((int)threadIdx.x < n) {
            long long v = p[threadIdx.x];
            if (v < 0 || v >= NN) atomicExch(&bad, 1);
        }
        __syncthreads();
        if (threadIdx.x == 0) g_is64 = bad ? 0 : 1;
    }
}

__device__ __forceinline__ int edge_at(const void* ei, int idx) {
    return g_is64 ? (int)((const long long*)ei)[idx] : ((const int*)ei)[idx];
}

// ---------------- CSR build ---------------------------------------------------
__global__ void k_hist(const void* ei, int EC) {
    int i = blockIdx.x * blockDim.x + threadIdx.x;
    if (i < EC) {
        int d = edge_at(ei, EC + i);
        if (d >= 0 && d < NN) atomicAdd(&g_deg[d], 1);
    }
}

__global__ void k_scan_block() {
    __shared__ int ws[32];
    int tid = threadIdx.x;
    int gid = blockIdx.x * 1024 + tid;
    int v = (gid < NN) ? g_deg[gid] : 0;
    int x = v;
    #pragma unroll
    for (int o = 1; o < 32; o <<= 1) {
        int t = __shfl_up_sync(0xffffffffu, x, o);
        if ((tid & 31) >= o) x += t;
    }
    if ((tid & 31) == 31) ws[tid >> 5] = x;
    __syncthreads();
    if (tid < 32) {
        int w = ws[tid];
        int y = w;
        #pragma unroll
        for (int o = 1; o < 32; o <<= 1) {
            int t = __shfl_up_sync(0xffffffffu, y, o);
            if (tid >= o) y += t;
        }
        ws[tid] = y - w;
    }
    __syncthreads();
    int incl = x + ws[tid >> 5];
    if (gid < NN) g_rowptr[gid] = incl - v;
    if (tid == 1023) g_bsum[blockIdx.x] = incl;
}

__global__ void k_scan_tops(int nblocks) {
    int lane = threadIdx.x;
    int run = 0;
    for (int base = 0; base < nblocks; base += 32) {
        int idx = base + lane;
        int v = (idx < nblocks) ? g_bsum[idx] : 0;
        int x = v;
        #pragma unroll
        for (int o = 1; o < 32; o <<= 1) {
            int t = __shfl_up_sync(0xffffffffu, x, o);
            if (lane >= o) x += t;
        }
        if (idx < nblocks) g_bsum[idx] = run + x - v;
        run += __shfl_sync(0xffffffffu, x, 31);
    }
}

__global__ void k_scan_fix(int EC) {
    int gid = blockIdx.x * 1024 + threadIdx.x;
    if (gid < NN) {
        int v = g_rowptr[gid] + g_bsum[gid >> 10];
        g_rowptr[gid] = v;
        g_fill[gid] = v;
    }
    if (gid == 0) g_rowptr[NN] = EC;
}

__global__ void k_scatter(const void* ei, int EC) {
    int i = blockIdx.x * blockDim.x + threadIdx.x;
    if (i < EC) {
        int s = edge_at(ei, i);
        int d = edge_at(ei, EC + i);
        if (d >= 0 && d < NN) {
            int p = atomicAdd(&g_fill[d], 1);
            if (p >= 0 && p < E_MAX) g_col[p] = s;
        }
    }
}

// ------- GEMM1 (128x64 tile, FFMA2 inner) + fused alpha epilogue --------------
__global__ void __launch_bounds__(256) k_gemm1(
    const float* __restrict__ X, const float* __restrict__ W,
    const float* __restrict__ att_s, const float* __restrict__ att_d) {
    __shared__ __align__(16) float sm[128 * 65];
    float* Ast = sm;                  // transposed: [kk][row], stride AST=132
    float* Bs  = sm + 32 * AST;
    int tid = threadIdx.x;
    int r0 = blockIdx.x * 128;
    int tx = tid & 15, ty = tid >> 4;

    unsigned long long acc2[4][4];
    unsigned long long z = pack2(0.f, 0.f);
    #pragma unroll
    for (int p = 0; p < 4; p++)
        #pragma unroll
        for (int c = 0; c < 4; c++) acc2[p][c] = z;

    for (int k0 = 0; k0 < F_IN; k0 += 32) {
        #pragma unroll
        for (int l = 0; l < 4; l++) {
            int slot = tid + l * 256;
            int row = slot >> 3;
            int f4 = slot & 7;
            int gr = r0 + row;
            float4 v = make_float4(0.f, 0.f, 0.f, 0.f);
            if (gr < NN) v = *(const float4*)(X + (long)gr * F_IN + k0 + f4 * 4);
            Ast[(f4 * 4 + 0) * AST + row] = v.x;
            Ast[(f4 * 4 + 1) * AST + row] = v.y;
            Ast[(f4 * 4 + 2) * AST + row] = v.z;
            Ast[(f4 * 4 + 3) * AST + row] = v.w;
        }
        #pragma unroll
        for (int l = 0; l < 2; l++) {
            int slot = tid + l * 256;
            int kk = slot >> 4;
            int cv = slot & 15;
            *(float4*)&Bs[kk * 64 + cv * 4] = *(const float4*)(W + (k0 + kk) * HID + cv * 4);
        }
        __syncthreads();
        #pragma unroll
        for (int kk = 0; kk < 32; kk++) {
            float4 bv = *(const float4*)&Bs[kk * 64 + tx * 4];
            unsigned long long br[4];
            br[0] = pack2(bv.x, bv.x);
            br[1] = pack2(bv.y, bv.y);
            br[2] = pack2(bv.z, bv.z);
            br[3] = pack2(bv.w, bv.w);
            const float* ab = Ast + kk * AST + ty * 8;
            #pragma unroll
            for (int p = 0; p < 4; p++) {
                unsigned long long ap = *(const unsigned long long*)(ab + 2 * p);
                acc2[p][0] = ffma2(ap, br[0], acc2[p][0]);
                acc2[p][1] = ffma2(ap, br[1], acc2[p][1]);
                acc2[p][2] = ffma2(ap, br[2], acc2[p][2]);
                acc2[p][3] = ffma2(ap, br[3], acc2[p][3]);
            }
        }
        __syncthreads();
    }

    float* hbuf = sm;                 // [128][65]
    #pragma unroll
    for (int p = 0; p < 4; p++) {
        float lo[4], hi[4];
        #pragma unroll
        for (int c = 0; c < 4; c++) unpack2(acc2[p][c], lo[c], hi[c]);
        int lr = ty * 8 + 2 * p;
        int gr = r0 + lr;
        #pragma unroll
        for (int c = 0; c < 4; c++) {
            hbuf[lr * 65 + tx * 4 + c] = lo[c];
            hbuf[(lr + 1) * 65 + tx * 4 + c] = hi[c];
        }
        if (gr < NN) {
            #pragma unroll
            for (int c = 0; c < 4; c++)
                g_h1[(long)gr * HID + tx * 4 + c] = lo[c];
        }
        if (gr + 1 < NN) {
            #pragma unroll
            for (int c = 0; c < 4; c++)
                g_h1[(long)(gr + 1) * HID + tx * 4 + c] = hi[c];
        }
    }
    __syncthreads();

    #pragma unroll
    for (int t = 0; t < 4; t++) {
        int item = tid + t * 256;
        int lr = item >> 3, h = item & 7;
        int gr = r0 + lr;
        if (gr < NN) {
            const float* hp = hbuf + lr * 65 + h * C1;
            float as = 0.f, ad = 0.f;
            #pragma unroll
            for (int c = 0; c < C1; c++) {
                float hv = hp[c];
                as += hv * __ldg(att_s + h * C1 + c);
                ad += hv * __ldg(att_d + h * C1 + c);
            }
            g_as1[gr * H1 + h] = as;
            g_ad1[gr * H1 + h] = ad;
        }
    }
}

// -------- layer 1 aggregation: shfl-free, 2-edge ILP, single pass + elu -------
// lane l owns channels (2l, 2l+1); both belong to head l>>2. Each lane computes
// its head's logit/exp itself (4 lanes redundant per head) -> weight AND
// denominator live in the right lane with no warp shuffle in the loop.
__global__ void k_agg1(const float* __restrict__ b1) {
    int warp = (blockIdx.x * blockDim.x + threadIdx.x) >> 5;
    int lane = threadIdx.x & 31;
    if (warp >= NN) return;
    int d = warp;
    int start = g_rowptr[d], end = g_rowptr[d + 1];
    int h = lane >> 2;                    // head for this lane's channel pair
    float ad = __ldg(g_ad1 + d * H1 + h);

    unsigned long long acc = pack2(0.f, 0.f);
    float den = 0.f;
    int n = end - start;
    int n2 = n & ~1;
    const int* cp = g_col + start;

    #pragma unroll 2
    for (int i = 0; i < n2; i += 2) {
        int s0 = __ldg(cp + i);
        int s1 = __ldg(cp + i + 1);
        float e0 = __ldg(g_as1 + s0 * H1 + h) + ad;
        float e1 = __ldg(g_as1 + s1 * H1 + h) + ad;
        e0 = (e0 > 0.f) ? e0 : NEG_SLOPE * e0;
        e1 = (e1 > 0.f) ? e1 : NEG_SLOPE * e1;
        float w0 = __expf(e0);
        float w1 = __expf(e1);
        unsigned long long hv0 = *(const unsigned long long*)(g_h1 + (long)s0 * HID + 2 * lane);
        unsigned long long hv1 = *(const unsigned long long*)(g_h1 + (long)s1 * HID + 2 * lane);
        den += w0 + w1;
        acc = ffma2(hv0, pack2(w0, w0), acc);
        acc = ffma2(hv1, pack2(w1, w1), acc);
    }
    if (n2 < n) {
        int s0 = __ldg(cp + n2);
        float e0 = __ldg(g_as1 + s0 * H1 + h) + ad;
        e0 = (e0 > 0.f) ? e0 : NEG_SLOPE * e0;
        float w0 = __expf(e0);
        unsigned long long hv0 = *(const unsigned long long*)(g_h1 + (long)s0 * HID + 2 * lane);
        den += w0;
        acc = ffma2(hv0, pack2(w0, w0), acc);
    }
    float inv = 1.0f / den;               // this lane's head => no shfl
    float lo, hi;
    unpack2(acc, lo, hi);
    float v0 = lo * inv + __ldg(b1 + 2 * lane);
    float v1 = hi * inv + __ldg(b1 + 2 * lane + 1);
    v0 = (v0 > 0.f) ? v0 : expm1f(v0);
    v1 = (v1 > 0.f) ? v1 : expm1f(v1);
    *(float2*)(g_h1o + (long)d * HID + 2 * lane) = make_float2(v0, v1);
}

// ---------------- GEMM2 (FFMA2 inner) + alpha2 --------------------------------
__global__ void __launch_bounds__(128) k_gemm2(
    const float* __restrict__ W2,
    const float* __restrict__ att_s2, const float* __restrict__ att_d2) {
    __shared__ __align__(16) float Xs[128][65];
    __shared__ __align__(16) float Ws[HID][NC];
    __shared__ float Sa[NC], Sd[NC];
    int tid = threadIdx.x;
    int r0 = blockIdx.x * 128;
    for (int f = tid; f < HID * NC; f += 128) Ws[f / NC][f % NC] = W2[f];
    if (tid < NC) { Sa[tid] = att_s2[tid]; Sd[tid] = att_d2[tid]; }
    for (int f = tid; f < 128 * HID; f += 128) {
        int rr = f >> 6, cc = f & 63;
        int gr = r0 + rr;
        Xs[rr][cc] = (gr < NN) ? g_h1o[(long)gr * HID + cc] : 0.f;
    }
    __syncthreads();
    int r = r0 + tid;
    unsigned long long acc2[NC / 2];
    unsigned long long z = pack2(0.f, 0.f);
    #pragma unroll
    for (int c = 0; c < NC / 2; c++) acc2[c] = z;
    #pragma unroll 4
    for (int k = 0; k < HID; k++) {
        float xv = Xs[tid][k];
        unsigned long long xp = pack2(xv, xv);
        const unsigned long long* wp = (const unsigned long long*)&Ws[k][0];
        #pragma unroll
        for (int c = 0; c < NC / 2; c++) acc2[c] = ffma2(xp, wp[c], acc2[c]);
    }
    if (r < NN) {
        float a = 0.f, dd = 0.f;
        #pragma unroll
        for (int c = 0; c < NC / 2; c++) {
            float lo, hi;
            unpack2(acc2[c], lo, hi);
            g_h2[(long)r * NC + 2 * c]     = lo;
            g_h2[(long)r * NC + 2 * c + 1] = hi;
            a  += lo * Sa[2 * c] + hi * Sa[2 * c + 1];
            dd += lo * Sd[2 * c] + hi * Sd[2 * c + 1];
        }
        g_as2[r] = a;
        g_ad2[r] = dd;
    }
}

// --------- layer 2 aggregation: 2-edge ILP, single pass + log_softmax ---------
__global__ void k_agg2(const float* __restrict__ b2, float* __restrict__ out) {
    int warp = (blockIdx.x * blockDim.x + threadIdx.x) >> 5;
    int lane = threadIdx.x & 31;
    if (warp >= NN) return;
    int d = warp;
    int start = g_rowptr[d], end = g_rowptr[d + 1];
    float ad = __ldg(g_ad2 + d);
    bool act = lane < 20;

    unsigned long long acc = pack2(0.f, 0.f);
    float den = 0.f;
    int n = end - start;
    int n2 = n & ~1;
    const int* cp = g_col + start;

    #pragma unroll 2
    for (int i = 0; i < n2; i += 2) {
        int s0 = __ldg(cp + i);
        int s1 = __ldg(cp + i + 1);
        float e0 = __ldg(g_as2 + s0) + ad;
        float e1 = __ldg(g_as2 + s1) + ad;
        e0 = (e0 > 0.f) ? e0 : NEG_SLOPE * e0;
        e1 = (e1 > 0.f) ? e1 : NEG_SLOPE * e1;
        float w0 = __expf(e0);
        float w1 = __expf(e1);
        den += w0 + w1;
        if (act) {
            unsigned long long hv0 = *(const unsigned long long*)(g_h2 + (long)s0 * NC + 2 * lane);
            unsigned long long hv1 = *(const unsigned long long*)(g_h2 + (long)s1 * NC + 2 * lane);
            acc = ffma2(hv0, pack2(w0, w0), acc);
            acc = ffma2(hv1, pack2(w1, w1), acc);
        }
    }
    if (n2 < n) {
        int s0 = __ldg(cp + n2);
        float e0 = __ldg(g_as2 + s0) + ad;
        e0 = (e0 > 0.f) ? e0 : NEG_SLOPE * e0;
        float w0 = __expf(e0);
        den += w0;
        if (act) {
            unsigned long long hv0 = *(const unsigned long long*)(g_h2 + (long)s0 * NC + 2 * lane);
            acc = ffma2(hv0, pack2(w0, w0), acc);
        }
    }
    float inv = 1.0f / den;
    float lo, hi;
    unpack2(acc, lo, hi);
    float v0 = act ? (lo * inv + __ldg(b2 + 2 * lane))     : -3.0e38f;
    float v1 = act ? (hi * inv + __ldg(b2 + 2 * lane + 1)) : -3.0e38f;

    float m = fmaxf(v0, v1);
    #pragma unroll
    for (int o = 16; o >= 1; o >>= 1) m = fmaxf(m, __shfl_xor_sync(0xffffffffu, m, o));
    float se = act ? (__expf(v0 - m) + __expf(v1 - m)) : 0.f;
    #pragma unroll
    for (int o = 16; o >= 1; o >>= 1) se += __shfl_xor_sync(0xffffffffu, se, o);
    float lse = m + logf(se);

    if (act)
        *(float2*)(out + (long)d * NC + 2 * lane) = make_float2(v0 - lse, v1 - lse);
}

// -----------------------------------------------------------------------------
extern "C" void kernel_launch(void* const* d_in, const int* in_sizes, int n_in,
                              void* d_out, int out_size) {
    const float* x        = (const float*)d_in[0];
    const float* W1       = (const float*)d_in[1];
    const float* att_src1 = (const float*)d_in[2];
    const float* att_dst1 = (const float*)d_in[3];
    const float* b1       = (const float*)d_in[4];
    const float* W2       = (const float*)d_in[5];
    const float* att_src2 = (const float*)d_in[6];
    const float* att_dst2 = (const float*)d_in[7];
    const float* b2       = (const float*)d_in[8];
    const void*  ei       = d_in[9];
    float* out = (float*)d_out;

    int EC = in_sizes[9] / 2;
    if (EC > E_MAX) EC = E_MAX;
    int nblocks = (NN + 1023) / 1024;

    cudaStream_t side;
    cudaStreamCreateWithFlags(&side, cudaStreamNonBlocking);
    cudaEvent_t evFork, evJoin;
    cudaEventCreateWithFlags(&evFork, cudaEventDisableTiming);
    cudaEventCreateWithFlags(&evJoin, cudaEventDisableTiming);

    cudaEventRecord(evFork, 0);
    cudaStreamWaitEvent(side, evFork, 0);
    k_gemm1<<<(NN + 127) / 128, 256, 0, side>>>(x, W1, att_src1, att_dst1);
    cudaEventRecord(evJoin, side);

    k_init<<<(NN + 255) / 256, 256>>>(ei, EC);
    k_hist<<<(EC + 255) / 256, 256>>>(ei, EC);
    k_scan_block<<<nblocks, 1024>>>();
    k_scan_tops<<<1, 32>>>(nblocks);
    k_scan_fix<<<nblocks, 1024>>>(EC);
    k_scatter<<<(EC + 255) / 256, 256>>>(ei, EC);

    cudaStreamWaitEvent(0, evJoin, 0);
    k_agg1<<<(NN * 32 + 255) / 256, 256>>>(b1);
    k_gemm2<<<(NN + 127) / 128, 128>>>(W2, att_src2, att_dst2);
    k_agg2<<<(NN * 32 + 255) / 256, 256>>>(b2, out);
}